// round 1
// baseline (speedup 1.0000x reference)
#include <cuda_runtime.h>
#include <cstddef>

// Problem constants (fixed shapes from reference setup_inputs)
constexpr int B = 32;
constexpr int C = 256;
constexpr int H = 64;
constexpr int W = 64;
constexpr int HW = H * W;          // 4096
constexpr int N = 2048;            // anchors per batch
constexpr int CHUNK = 8;           // channels per CTA
constexpr int NCHUNKS = C / CHUNK; // 32
constexpr int THREADS = 512;
constexpr int SMEM_FLOATS = CHUNK * HW;          // 32768 floats
constexpr size_t SMEM_BYTES = SMEM_FLOATS * 4;   // 128 KB

__global__ __launch_bounds__(THREADS, 1)
void bilinear_gather_kernel(const float* __restrict__ fm,
                            const float* __restrict__ anchors,
                            float* __restrict__ out)
{
    extern __shared__ float s[];   // [CHUNK][HW]

    const int blk   = blockIdx.x;
    const int b     = blk / NCHUNKS;
    const int chunk = blk % NCHUNKS;

    // ---- Stage the (b, chunk) channel slice into smem: coalesced float4 copy.
    // Each fm byte is read exactly once across the whole grid -> HBM floor.
    {
        const float4* __restrict__ src4 =
            reinterpret_cast<const float4*>(fm + ((size_t)b * C + (size_t)chunk * CHUNK) * HW);
        float4* __restrict__ s4 = reinterpret_cast<float4*>(s);
        #pragma unroll
        for (int i = threadIdx.x; i < SMEM_FLOATS / 4; i += THREADS) {
            s4[i] = src4[i];
        }
    }
    __syncthreads();

    const float2* __restrict__ anc2 =
        reinterpret_cast<const float2*>(anchors + (size_t)b * N * 2);
    float* __restrict__ outb = out + (size_t)b * N * C + (size_t)chunk * CHUNK;

    // ---- Gather phase: one thread per anchor (strided), 8 channels each.
    for (int n = threadIdx.x; n < N; n += THREADS) {
        float2 a = anc2[n];                       // (x, y) normalized
        float px = fminf(fmaxf(a.x * 63.0f, 0.0f), 63.0f);
        float py = fminf(fmaxf(a.y * 63.0f, 0.0f), 63.0f);

        float fx = floorf(px), fy = floorf(py);
        float cx = ceilf(px),  cy = ceilf(py);    // ceil, matching reference (rb==lt when integral)
        int xl = (int)fx, yl = (int)fy;
        int xr = (int)cx, yr = (int)cy;
        float dx = px - fx;
        float dy = py - fy;

        int i_lt = yl * H + xl;
        int i_rt = yl * H + xr;
        int i_lb = yr * H + xl;
        int i_rb = yr * H + xr;

        float res[CHUNK];
        #pragma unroll
        for (int c = 0; c < CHUNK; ++c) {
            const float* __restrict__ sc = s + c * HW;
            float vlt = sc[i_lt];
            float vrt = sc[i_rt];
            float vlb = sc[i_lb];
            float vrb = sc[i_rb];
            float vt = vlt + (vrt - vlt) * dx;
            float vb = vlb + (vrb - vlb) * dx;
            res[c]   = vt + (vb - vt) * dy;
        }

        // 32 contiguous bytes per anchor -> full-sector writes, no amplification.
        float4* __restrict__ o4 = reinterpret_cast<float4*>(outb + (size_t)n * C);
        o4[0] = make_float4(res[0], res[1], res[2], res[3]);
        o4[1] = make_float4(res[4], res[5], res[6], res[7]);
    }
}

extern "C" void kernel_launch(void* const* d_in, const int* in_sizes, int n_in,
                              void* d_out, int out_size)
{
    const float* fm      = (const float*)d_in[0];  // (32,256,64,64) fp32
    const float* anchors = (const float*)d_in[1];  // (32,2048,2) fp32
    float* out           = (float*)d_out;          // (32,2048,256) fp32

    // Opt in to 128 KB dynamic shared memory (host-side attr set; not a stream op,
    // safe under graph capture).
    cudaFuncSetAttribute(bilinear_gather_kernel,
                         cudaFuncAttributeMaxDynamicSharedMemorySize,
                         (int)SMEM_BYTES);

    dim3 grid(B * NCHUNKS);   // 1024 CTAs
    dim3 block(THREADS);
    bilinear_gather_kernel<<<grid, block, SMEM_BYTES>>>(fm, anchors, out);
}

// round 2
// speedup vs baseline: 1.0164x; 1.0164x over previous
#include <cuda_runtime.h>
#include <cstddef>

// Problem constants (fixed shapes from reference setup_inputs)
constexpr int B = 32;
constexpr int C = 256;
constexpr int H = 64;
constexpr int W = 64;
constexpr int HW = H * W;          // 4096
constexpr int N = 2048;            // anchors per batch
constexpr int CHUNK = 8;           // channels per CTA
constexpr int NCHUNKS = C / CHUNK; // 32
constexpr int THREADS = 512;
constexpr int SMEM_FLOATS = CHUNK * HW;          // 32768 floats
constexpr size_t SMEM_BYTES = SMEM_FLOATS * 4;   // 128 KB

__global__ __launch_bounds__(THREADS, 1)
void bilinear_gather_kernel(const float* __restrict__ fm,
                            const float* __restrict__ anchors,
                            float* __restrict__ out)
{
    extern __shared__ float s[];   // [CHUNK][HW]

    const int blk   = blockIdx.x;
    const int b     = blk / NCHUNKS;
    const int chunk = blk % NCHUNKS;

    // ---- Stage the (b, chunk) channel slice into smem: coalesced float4 copy.
    // Each fm byte is read exactly once across the whole grid -> HBM floor.
    {
        const float4* __restrict__ src4 =
            reinterpret_cast<const float4*>(fm + ((size_t)b * C + (size_t)chunk * CHUNK) * HW);
        float4* __restrict__ s4 = reinterpret_cast<float4*>(s);
        #pragma unroll
        for (int i = threadIdx.x; i < SMEM_FLOATS / 4; i += THREADS) {
            s4[i] = src4[i];
        }
    }
    __syncthreads();

    const float2* __restrict__ anc2 =
        reinterpret_cast<const float2*>(anchors + (size_t)b * N * 2);
    float* __restrict__ outb = out + (size_t)b * N * C + (size_t)chunk * CHUNK;

    // ---- Gather phase: one thread per anchor (strided), 8 channels each.
    for (int n = threadIdx.x; n < N; n += THREADS) {
        float2 a = anc2[n];                       // (x, y) normalized
        float px = fminf(fmaxf(a.x * 63.0f, 0.0f), 63.0f);
        float py = fminf(fmaxf(a.y * 63.0f, 0.0f), 63.0f);

        float fx = floorf(px), fy = floorf(py);
        float cx = ceilf(px),  cy = ceilf(py);    // ceil, matching reference (rb==lt when integral)
        int xl = (int)fx, yl = (int)fy;
        int xr = (int)cx, yr = (int)cy;
        float dx = px - fx;
        float dy = py - fy;

        int i_lt = yl * H + xl;
        int i_rt = yl * H + xr;
        int i_lb = yr * H + xl;
        int i_rb = yr * H + xr;

        float res[CHUNK];
        #pragma unroll
        for (int c = 0; c < CHUNK; ++c) {
            const float* __restrict__ sc = s + c * HW;
            float vlt = sc[i_lt];
            float vrt = sc[i_rt];
            float vlb = sc[i_lb];
            float vrb = sc[i_rb];
            float vt = vlt + (vrt - vlt) * dx;
            float vb = vlb + (vrb - vlb) * dx;
            res[c]   = vt + (vb - vt) * dy;
        }

        // 32 contiguous bytes per anchor -> full-sector writes, no amplification.
        float4* __restrict__ o4 = reinterpret_cast<float4*>(outb + (size_t)n * C);
        o4[0] = make_float4(res[0], res[1], res[2], res[3]);
        o4[1] = make_float4(res[4], res[5], res[6], res[7]);
    }
}

extern "C" void kernel_launch(void* const* d_in, const int* in_sizes, int n_in,
                              void* d_out, int out_size)
{
    const float* fm      = (const float*)d_in[0];  // (32,256,64,64) fp32
    const float* anchors = (const float*)d_in[1];  // (32,2048,2) fp32
    float* out           = (float*)d_out;          // (32,2048,256) fp32

    // Opt in to 128 KB dynamic shared memory (host-side attr set; not a stream op,
    // safe under graph capture).
    cudaFuncSetAttribute(bilinear_gather_kernel,
                         cudaFuncAttributeMaxDynamicSharedMemorySize,
                         (int)SMEM_BYTES);

    dim3 grid(B * NCHUNKS);   // 1024 CTAs
    dim3 block(THREADS);
    bilinear_gather_kernel<<<grid, block, SMEM_BYTES>>>(fm, anchors, out);
}